// round 15
// baseline (speedup 1.0000x reference)
#include <cuda_runtime.h>
#include <cuda_fp16.h>
#include <cstdint>

#define T_SEQ 128
#define E_DIM 256
#define H_DIM 64
#define NSM   148

// ---- SMEM byte layout (one 512-thread CTA, 205824 B) ----
#define SW0_B  0u          // W ring slot 0 [192][72]h
#define SW1_B  27648u      // W ring slot 1
#define SX_B   55296u      // x pass-chunk [64][72]h (producer scratch)
#define QKV0_B 64512u      // QKV buf 0 [128][200]h
#define QKV1_B 115712u     // QKV buf 1
#define SP_B   166912u     // P [128][136]h (consumer)
#define PM_B   201728u     // float[4][128]
#define PS_B   203776u     // float[4][128]
#define SMEM_BYTES 205824u

#define LDA 144            // x row stride bytes
#define LDW 144            // W row stride bytes
#define LDQ 400            // QKV row stride bytes
#define LDP 272            // P row stride bytes
#define W_EC 27648u

// log2(e)/8  (softmax in log2 domain; 1/sqrt(64) folded in)
#define SCL 0.18033688f

// W pre-converted fp16: [ec(4)][n(192)=Wq|Wk|Wv rows][k(72)]
__device__ __align__(16) __half g_wt[4 * 192 * 72];

// ---------------- helpers ----------------
__device__ __forceinline__ uint32_t smem_u32(const void* p) {
    uint32_t a;
    asm("{ .reg .u64 t; cvta.to.shared.u64 t, %1; cvt.u32.u64 %0, t; }" : "=r"(a) : "l"(p));
    return a;
}
__device__ __forceinline__ uint32_t pack2(float lo, float hi) {
    uint32_t r;
    asm("cvt.rn.f16x2.f32 %0, %1, %2;" : "=r"(r) : "f"(hi), "f"(lo));  // first src -> high
    return r;
}
__device__ __forceinline__ float fex2(float x) {
    float r;
    asm("ex2.approx.f32 %0, %1;" : "=f"(r) : "f"(x));
    return r;
}
#define LDSM_X4(R, a) \
    asm volatile("ldmatrix.sync.aligned.m8n8.x4.shared.b16 {%0,%1,%2,%3}, [%4];" \
        : "=r"((R)[0]), "=r"((R)[1]), "=r"((R)[2]), "=r"((R)[3]) : "r"(a))
#define LDSM_X4T(R, a) \
    asm volatile("ldmatrix.sync.aligned.m8n8.x4.trans.shared.b16 {%0,%1,%2,%3}, [%4];" \
        : "=r"((R)[0]), "=r"((R)[1]), "=r"((R)[2]), "=r"((R)[3]) : "r"(a))
#define MMA16816(D, A, B0, B1) \
    asm volatile("mma.sync.aligned.m16n8k16.row.col.f32.f16.f16.f32 " \
        "{%0,%1,%2,%3}, {%4,%5,%6,%7}, {%8,%9}, {%0,%1,%2,%3};" \
        : "+f"((D)[0]), "+f"((D)[1]), "+f"((D)[2]), "+f"((D)[3]) \
        : "r"((A)[0]), "r"((A)[1]), "r"((A)[2]), "r"((A)[3]), "r"(B0), "r"(B1))
#define CP_ASYNC16(dst, src) \
    asm volatile("cp.async.cg.shared.global [%0], [%1], 16;" :: "r"(dst), "l"(src))
#define CP_COMMIT()  asm volatile("cp.async.commit_group;" ::: "memory")
#define CP_WAITN(n)  asm volatile("cp.async.wait_group %0;" :: "n"(n) : "memory")

// producer-group / consumer-group named barriers (256 threads each)
#define BARP() asm volatile("bar.sync 1, 256;" ::: "memory")
#define BARC() asm volatile("bar.sync 2, 256;" ::: "memory")

// fetch W chunk c into ring slot s (issued by 256 producer threads)
#define FETCH_W(c, s) do {                                                        \
    const char* _ws = reinterpret_cast<const char*>(g_wt) + (size_t)(c) * W_EC;   \
    _Pragma("unroll")                                                             \
    for (int _i = 0; _i < 7; _i++) {                                              \
        int _idx = tid + _i * 256;                                                \
        if (_idx < 1728)                                                          \
            CP_ASYNC16(sbase + ((s) ? SW1_B : SW0_B) + _idx * 16, _ws + _idx * 16); \
    }                                                                             \
    CP_COMMIT();                                                                  \
} while (0)

// ---------------- W prep: fp32 [E][H] -> fp16 tiles [ec][n][72] ----------------
__global__ void prep_w_kernel(const float* __restrict__ Wq,
                              const float* __restrict__ Wk,
                              const float* __restrict__ Wv) {
    int blk = blockIdx.x;             // ec*3 + m
    int ec = blk / 3, m = blk % 3;
    const float* W = (m == 0) ? Wq : (m == 1) ? Wk : Wv;
#pragma unroll
    for (int i = 0; i < 16; i++) {
        int e = threadIdx.x + i * 256;      // 0..4095
        int h = e >> 6, k = e & 63;
        g_wt[((size_t)ec * 192 + m * 64 + h) * 72 + k] =
            __float2half_rn(W[(ec * 64 + k) * H_DIM + h]);
    }
}

// ---------------- main kernel: persistent, warp-specialized ----------------
__global__ __launch_bounds__(512, 1)
void attn_fp16_kernel(const float* __restrict__ x, float* __restrict__ out, int B) {
    extern __shared__ char smem[];
    const uint32_t sbase = smem_u32(smem);
    const int tid = threadIdx.x, warp = tid >> 5, lane = tid & 31;
    const int g = lane >> 2, t = lane & 3;
    const int cw = warp & 7;
    const bool prod = (warp < 8);
    // producer tiling: 2x4 warps over 64 rows x 192 cols (per M-pass)
    const int wmP = cw & 1;
    const int n0  = (cw >> 1) * 48;
    // consumer tiling: 2x4 warps over 128 rows x 128 cols
    const int wm = cw & 1, wn = cw >> 1;
    const int m0 = wm * 64, n02 = wn * 32, n03 = wn * 16;

    const int cta = blockIdx.x, stride = gridDim.x;
    const int nb = (B - cta + stride - 1) / stride;   // batches for this CTA

    float* pm = reinterpret_cast<float*>(smem + PM_B);
    float* ps = reinterpret_cast<float*>(smem + PS_B);

    for (int i = 0; i <= nb; i++) {
        if (prod) {
            // ======== PRODUCER: QKV(batch i) -> qkv[i&1] ========
            if (i < nb) {
                const size_t b = (size_t)cta + (size_t)i * stride;
                const float* xb = x + b * (size_t)(T_SEQ * E_DIM);
                char* qkv = smem + ((i & 1) ? QKV1_B : QKV0_B);

                FETCH_W(0, 0);
                float acc1[2][6][4];
#pragma unroll
                for (int p1 = 0; p1 < 2; p1++)
#pragma unroll
                    for (int p2 = 0; p2 < 6; p2++)
#pragma unroll
                        for (int p3 = 0; p3 < 4; p3++) acc1[p1][p2][p3] = 0.f;

                const uint32_t boffs = (uint32_t)(n0 + ((lane >> 4) << 3) + (lane & 7)) * LDW
                                     + ((lane >> 3) & 1) * 16;
                const uint32_t abase = sbase + SX_B
                                     + (uint32_t)(wmP * 32 + (lane & 15)) * LDA
                                     + (lane >> 4) * 16;
#pragma unroll 1
                for (int u = 0; u < 8; u++) {          // 2 M-passes x 4 E-chunks
                    const int p = u >> 2, ec = u & 3;
                    // x chunk [64 rows of pass p][64 cols of ec] -> regs
                    float4 f0[2], f1[2];
#pragma unroll
                    for (int j = 0; j < 2; j++) {
                        int q = tid + j * 256, row = q >> 3, c8 = q & 7;
                        const float* src = xb + (size_t)(p * 64 + row) * E_DIM + ec * 64 + c8 * 8;
                        f0[j] = *reinterpret_cast<const float4*>(src);
                        f1[j] = *reinterpret_cast<const float4*>(src + 4);
                    }
                    BARP();   // all producer warps done reading SX / W-slot[(u+1)&1]
                    if (u < 7) FETCH_W((u + 1) & 3, (u + 1) & 1);
#pragma unroll
                    for (int j = 0; j < 2; j++) {
                        int q = tid + j * 256, row = q >> 3, c8 = q & 7;
                        uint4 uu;
                        uu.x = pack2(f0[j].x, f0[j].y);  uu.y = pack2(f0[j].z, f0[j].w);
                        uu.z = pack2(f1[j].x, f1[j].y);  uu.w = pack2(f1[j].z, f1[j].w);
                        *reinterpret_cast<uint4*>(smem + SX_B + row * LDA + c8 * 16) = uu;
                    }
                    if (u < 7) { CP_WAITN(1); } else { CP_WAITN(0); }
                    BARP();   // publish x STS + W cp.async to all producer warps

                    const uint32_t wb = sbase + ((u & 1) ? SW1_B : SW0_B) + boffs;
#pragma unroll
                    for (int kt = 0; kt < 4; kt++) {
                        uint32_t a[2][4], bf[3][4];
#pragma unroll
                        for (int mt = 0; mt < 2; mt++)
                            LDSM_X4(a[mt], abase + mt * 16 * LDA + kt * 32);
#pragma unroll
                        for (int bt = 0; bt < 3; bt++)
                            LDSM_X4(bf[bt], wb + bt * 16 * LDW + kt * 32);
#pragma unroll
                        for (int mt = 0; mt < 2; mt++)
#pragma unroll
                            for (int nt = 0; nt < 6; nt++)
                                MMA16816(acc1[mt][nt], a[mt], bf[nt >> 1][(nt & 1) * 2],
                                         bf[nt >> 1][(nt & 1) * 2 + 1]);
                    }

                    if ((u & 3) == 3) {   // end of pass p: write rows p*64..p*64+63
#pragma unroll
                        for (int mt = 0; mt < 2; mt++) {
                            int rlo = p * 64 + wmP * 32 + mt * 16 + g, rhi = rlo + 8;
#pragma unroll
                            for (int nt = 0; nt < 6; nt++) {
                                int cg = n0 + nt * 8 + t * 2;
                                *reinterpret_cast<uint32_t*>(qkv + rlo * LDQ + cg * 2) =
                                    pack2(acc1[mt][nt][0], acc1[mt][nt][1]);
                                *reinterpret_cast<uint32_t*>(qkv + rhi * LDQ + cg * 2) =
                                    pack2(acc1[mt][nt][2], acc1[mt][nt][3]);
                                acc1[mt][nt][0] = 0.f; acc1[mt][nt][1] = 0.f;
                                acc1[mt][nt][2] = 0.f; acc1[mt][nt][3] = 0.f;
                            }
                        }
                    }
                }
            }
        } else {
            // ======== CONSUMER: attention(batch i-1) from qkv[(i-1)&1] ========
            if (i >= 1) {
                const size_t bc = (size_t)cta + (size_t)(i - 1) * stride;
                const uint32_t cb = sbase + (((i - 1) & 1) ? QKV1_B : QKV0_B);
                const char* cbp = smem + (((i - 1) & 1) ? QKV1_B : QKV0_B);

                // ---- S = Q K^T, causal softmax partials ----
                const bool active = (n02 <= m0 + 63);
                float acc2[4][4][4];
                float fscale[4][2];
                if (active) {
#pragma unroll
                    for (int p1 = 0; p1 < 4; p1++)
#pragma unroll
                        for (int p2 = 0; p2 < 4; p2++)
#pragma unroll
                            for (int p3 = 0; p3 < 4; p3++) acc2[p1][p2][p3] = 0.f;

                    const uint32_t arow = cb + (uint32_t)(m0 + (lane & 15)) * LDQ
                                        + (lane >> 4) * 16;
                    const uint32_t brow = cb + (uint32_t)(n02 + ((lane >> 4) << 3) + (lane & 7)) * LDQ
                                        + 128 + ((lane >> 3) & 1) * 16;
#pragma unroll
                    for (int kt = 0; kt < 4; kt++) {
                        uint32_t a[4][4], bf[2][4];
#pragma unroll
                        for (int mt = 0; mt < 4; mt++)
                            LDSM_X4(a[mt], arow + mt * 16 * LDQ + kt * 32);
#pragma unroll
                        for (int bt = 0; bt < 2; bt++)
                            LDSM_X4(bf[bt], brow + bt * 16 * LDQ + kt * 32);
#pragma unroll
                        for (int mt = 0; mt < 4; mt++)
#pragma unroll
                            for (int nt = 0; nt < 4; nt++)
                                MMA16816(acc2[mt][nt], a[mt], bf[nt >> 1][(nt & 1) * 2],
                                         bf[nt >> 1][(nt & 1) * 2 + 1]);
                    }
#pragma unroll
                    for (int mt = 0; mt < 4; mt++) {
                        int rlo = m0 + mt * 16 + g, rhi = rlo + 8;
                        float mlo = -1e30f, mhi = -1e30f;
#pragma unroll
                        for (int nt = 0; nt < 4; nt++)
#pragma unroll
                            for (int j = 0; j < 2; j++) {
                                int c = n02 + nt * 8 + t * 2 + j;
                                float v0 = acc2[mt][nt][j] * SCL;
                                v0 = (c <= rlo) ? v0 : -1e30f;
                                acc2[mt][nt][j] = v0; mlo = fmaxf(mlo, v0);
                                float v1 = acc2[mt][nt][2 + j] * SCL;
                                v1 = (c <= rhi) ? v1 : -1e30f;
                                acc2[mt][nt][2 + j] = v1; mhi = fmaxf(mhi, v1);
                            }
                        mlo = fmaxf(mlo, __shfl_xor_sync(0xffffffffu, mlo, 1));
                        mlo = fmaxf(mlo, __shfl_xor_sync(0xffffffffu, mlo, 2));
                        mhi = fmaxf(mhi, __shfl_xor_sync(0xffffffffu, mhi, 1));
                        mhi = fmaxf(mhi, __shfl_xor_sync(0xffffffffu, mhi, 2));
                        float slo = 0.f, shi = 0.f;
#pragma unroll
                        for (int nt = 0; nt < 4; nt++)
#pragma unroll
                            for (int j = 0; j < 2; j++) {
                                float e0 = fex2(acc2[mt][nt][j] - mlo);
                                float e1 = fex2(acc2[mt][nt][2 + j] - mhi);
                                acc2[mt][nt][j] = e0;  acc2[mt][nt][2 + j] = e1;
                                slo += e0; shi += e1;
                            }
                        slo += __shfl_xor_sync(0xffffffffu, slo, 1);
                        slo += __shfl_xor_sync(0xffffffffu, slo, 2);
                        shi += __shfl_xor_sync(0xffffffffu, shi, 1);
                        shi += __shfl_xor_sync(0xffffffffu, shi, 2);
                        if (t == 0) {
                            pm[wn * 128 + rlo] = mlo;  pm[wn * 128 + rhi] = mhi;
                            ps[wn * 128 + rlo] = slo;  ps[wn * 128 + rhi] = shi;
                        }
                        fscale[mt][0] = mlo;  fscale[mt][1] = mhi;
                    }
                } else {
                    if (t == 0) {
#pragma unroll
                        for (int mt = 0; mt < 4; mt++) {
                            int rlo = m0 + mt * 16 + g, rhi = rlo + 8;
                            pm[wn * 128 + rlo] = -1e30f;  pm[wn * 128 + rhi] = -1e30f;
                            ps[wn * 128 + rlo] = 0.f;     ps[wn * 128 + rhi] = 0.f;
                        }
                    }
                }
                BARC();

                // ---- combine partials, write P ----
                if (active) {
#pragma unroll
                    for (int mt = 0; mt < 4; mt++) {
                        int rlo = m0 + mt * 16 + g, rhi = rlo + 8;
                        float M0 = pm[rlo], M1 = pm[128 + rlo], M2 = pm[256 + rlo], M3 = pm[384 + rlo];
                        float Mlo = fmaxf(fmaxf(M0, M1), fmaxf(M2, M3));
                        float Zlo = ps[rlo] * fex2(M0 - Mlo) + ps[128 + rlo] * fex2(M1 - Mlo)
                                  + ps[256 + rlo] * fex2(M2 - Mlo) + ps[384 + rlo] * fex2(M3 - Mlo);
                        float N0 = pm[rhi], N1 = pm[128 + rhi], N2 = pm[256 + rhi], N3 = pm[384 + rhi];
                        float Mhi = fmaxf(fmaxf(N0, N1), fmaxf(N2, N3));
                        float Zhi = ps[rhi] * fex2(N0 - Mhi) + ps[128 + rhi] * fex2(N1 - Mhi)
                                  + ps[256 + rhi] * fex2(N2 - Mhi) + ps[384 + rhi] * fex2(N3 - Mhi);
                        float flo = fex2(fscale[mt][0] - Mlo) / Zlo;
                        float fhi = fex2(fscale[mt][1] - Mhi) / Zhi;
#pragma unroll
                        for (int nt = 0; nt < 4; nt++) {
                            int c = n02 + nt * 8 + t * 2;
                            *reinterpret_cast<uint32_t*>(smem + SP_B + rlo * LDP + c * 2) =
                                pack2(acc2[mt][nt][0] * flo, acc2[mt][nt][1] * flo);
                            *reinterpret_cast<uint32_t*>(smem + SP_B + rhi * LDP + c * 2) =
                                pack2(acc2[mt][nt][2] * fhi, acc2[mt][nt][3] * fhi);
                        }
                    }
                }
                BARC();

                // ---- O = P V  (causal kt-skip) ----
                float acc3[4][2][4];
#pragma unroll
                for (int p1 = 0; p1 < 4; p1++)
#pragma unroll
                    for (int p2 = 0; p2 < 2; p2++)
#pragma unroll
                        for (int p3 = 0; p3 < 4; p3++) acc3[p1][p2][p3] = 0.f;

                const uint32_t prow = sbase + SP_B + (uint32_t)(m0 + (lane & 15)) * LDP
                                    + (lane >> 4) * 16;
                const uint32_t vbase = cb + (uint32_t)(((lane >> 3) & 1) * 8 + (lane & 7)) * LDQ
                                     + 256 + (lane >> 4) * 16 + n03 * 2;
                const int ktend = 4 + 4 * wm;
#pragma unroll 4
                for (int kt = 0; kt < ktend; kt++) {
                    uint32_t a3[4][4], bv[4];
#pragma unroll
                    for (int mt = 0; mt < 4; mt++)
                        LDSM_X4(a3[mt], prow + mt * 16 * LDP + kt * 32);
                    LDSM_X4T(bv, vbase + kt * 16 * LDQ);
#pragma unroll
                    for (int mt = 0; mt < 4; mt++) {
                        MMA16816(acc3[mt][0], a3[mt], bv[0], bv[1]);
                        MMA16816(acc3[mt][1], a3[mt], bv[2], bv[3]);
                    }
                }

                float* ob = out + bc * (size_t)(T_SEQ * H_DIM);
#pragma unroll
                for (int mt = 0; mt < 4; mt++) {
                    int rlo = m0 + mt * 16 + g, rhi = rlo + 8;
#pragma unroll
                    for (int nt = 0; nt < 2; nt++) {
                        int c = n03 + nt * 8 + t * 2;
                        *reinterpret_cast<float2*>(ob + rlo * H_DIM + c) =
                            make_float2(acc3[mt][nt][0], acc3[mt][nt][1]);
                        *reinterpret_cast<float2*>(ob + rhi * H_DIM + c) =
                            make_float2(acc3[mt][nt][2], acc3[mt][nt][3]);
                    }
                }
                (void)cbp;
            }
        }
        __syncthreads();   // stage handoff: QKV buffers swap roles
    }
}

extern "C" void kernel_launch(void* const* d_in, const int* in_sizes, int n_in,
                              void* d_out, int out_size) {
    const float* x  = (const float*)d_in[0];
    const float* Wq = (const float*)d_in[1];
    const float* Wk = (const float*)d_in[2];
    const float* Wv = (const float*)d_in[3];
    float* out = (float*)d_out;

    int B = in_sizes[0] / (T_SEQ * E_DIM);   // 4096

    cudaFuncSetAttribute(attn_fp16_kernel,
                         cudaFuncAttributeMaxDynamicSharedMemorySize,
                         (int)SMEM_BYTES);

    prep_w_kernel<<<12, 256>>>(Wq, Wk, Wv);
    attn_fp16_kernel<<<NSM, 512, SMEM_BYTES>>>(x, out, B);
}

// round 16
// speedup vs baseline: 1.1524x; 1.1524x over previous
#include <cuda_runtime.h>
#include <cuda_fp16.h>
#include <cstdint>

#define T_SEQ 128
#define E_DIM 256
#define H_DIM 64

// ---- SMEM byte layout (one 512-thread CTA, 223232 B, 1 CTA/SM) ----
#define SW_B   0u          // W resident [4 ec][192][72]h = 110592
#define SX_B   110592u     // x chunk buf [128][72]h = 18432
#define SQ_B   129024u     // Q [128][72]h
#define SK_B   147456u     // K [128][72]h
#define SV_B   165888u     // V [128][72]h
#define SP_B   184320u     // P [128][136]h = 34816
#define PM_B   219136u     // float[4][128]
#define PS_B   221184u     // float[4][128]
#define SMEM_BYTES 223232u

#define LDA 144            // x / QKV tile row stride (bytes)
#define LDW 144            // W row stride (bytes)
#define LDP 272            // P row stride (bytes)
#define W_EC 27648u        // bytes per W E-chunk [192][72]h

// log2(e)/8  (softmax in log2 domain; 1/sqrt(64) folded in)
#define SCL 0.18033688f

// W pre-converted fp16, pre-transposed: [ec(4)][n(192)=Wq|Wk|Wv rows][k(72)]
__device__ __align__(16) __half g_wt[4 * 192 * 72];

// ---------------- helpers ----------------
__device__ __forceinline__ uint32_t smem_u32(const void* p) {
    uint32_t a;
    asm("{ .reg .u64 t; cvta.to.shared.u64 t, %1; cvt.u32.u64 %0, t; }" : "=r"(a) : "l"(p));
    return a;
}
__device__ __forceinline__ uint32_t pack2(float lo, float hi) {
    uint32_t r;
    asm("cvt.rn.f16x2.f32 %0, %1, %2;" : "=r"(r) : "f"(hi), "f"(lo));  // first src -> high
    return r;
}
__device__ __forceinline__ float fex2(float x) {
    float r;
    asm("ex2.approx.f32 %0, %1;" : "=f"(r) : "f"(x));
    return r;
}
#define LDSM_X4(R, a) \
    asm volatile("ldmatrix.sync.aligned.m8n8.x4.shared.b16 {%0,%1,%2,%3}, [%4];" \
        : "=r"((R)[0]), "=r"((R)[1]), "=r"((R)[2]), "=r"((R)[3]) : "r"(a))
#define LDSM_X4T(R, a) \
    asm volatile("ldmatrix.sync.aligned.m8n8.x4.trans.shared.b16 {%0,%1,%2,%3}, [%4];" \
        : "=r"((R)[0]), "=r"((R)[1]), "=r"((R)[2]), "=r"((R)[3]) : "r"(a))
#define MMA16816(D, A, B0, B1) \
    asm volatile("mma.sync.aligned.m16n8k16.row.col.f32.f16.f16.f32 " \
        "{%0,%1,%2,%3}, {%4,%5,%6,%7}, {%8,%9}, {%0,%1,%2,%3};" \
        : "+f"((D)[0]), "+f"((D)[1]), "+f"((D)[2]), "+f"((D)[3]) \
        : "r"((A)[0]), "r"((A)[1]), "r"((A)[2]), "r"((A)[3]), "r"(B0), "r"(B1))
#define CP_ASYNC16(dst, src) \
    asm volatile("cp.async.cg.shared.global [%0], [%1], 16;" :: "r"(dst), "l"(src))
#define CP_COMMIT()  asm volatile("cp.async.commit_group;" ::: "memory")
#define CP_WAIT0()   asm volatile("cp.async.wait_group 0;" ::: "memory")

// ---------------- W prep: fp32 [E][H] -> fp16 tiles [ec][n][72] ----------------
__global__ void prep_w_kernel(const float* __restrict__ Wq,
                              const float* __restrict__ Wk,
                              const float* __restrict__ Wv) {
    int blk = blockIdx.x;             // ec*3 + m
    int ec = blk / 3, m = blk % 3;
    const float* W = (m == 0) ? Wq : (m == 1) ? Wk : Wv;
#pragma unroll
    for (int i = 0; i < 16; i++) {
        int e = threadIdx.x + i * 256;      // 0..4095
        int h = e >> 6, k = e & 63;
        g_wt[((size_t)ec * 192 + m * 64 + h) * 72 + k] =
            __float2half_rn(W[(ec * 64 + k) * H_DIM + h]);
    }
}

// ---------------- main kernel: 512 threads, 16 warps, 2 batches/CTA ----------------
__global__ __launch_bounds__(512, 1)
void attn_fp16_kernel(const float* __restrict__ x, float* __restrict__ out, int B) {
    extern __shared__ char smem[];
    const uint32_t sbase = smem_u32(smem);
    const int tid = threadIdx.x, warp = tid >> 5, lane = tid & 31;
    const int g = lane >> 2, t = lane & 3;
    const int wm = warp & 3, wn = warp >> 2;     // 4 x 4 warp grid
    const int m0 = wm * 32;
    const size_t b0 = (size_t)blockIdx.x * 2;

    float* pm = reinterpret_cast<float*>(smem + PM_B);
    float* ps = reinterpret_cast<float*>(smem + PS_B);

    // ---- prologue: fetch ALL of W (one commit), stage x chunk0 of batch b0 ----
    {
        const char* wsrc = reinterpret_cast<const char*>(g_wt);
#pragma unroll
        for (int i = 0; i < 14; i++) {
            int idx = tid + i * 512;
            if (idx < 6912) CP_ASYNC16(sbase + SW_B + idx * 16, wsrc + idx * 16);
        }
        CP_COMMIT();
        const float* xb = x + b0 * (size_t)(T_SEQ * E_DIM);
        float4 f0[2], f1[2];
#pragma unroll
        for (int j = 0; j < 2; j++) {
            int q = tid + j * 512, r = q >> 3, c8 = q & 7;
            const float* p = xb + r * E_DIM + c8 * 8;
            f0[j] = *reinterpret_cast<const float4*>(p);
            f1[j] = *reinterpret_cast<const float4*>(p + 4);
        }
#pragma unroll
        for (int j = 0; j < 2; j++) {
            int q = tid + j * 512, r = q >> 3, c8 = q & 7;
            uint4 u;
            u.x = pack2(f0[j].x, f0[j].y);  u.y = pack2(f0[j].z, f0[j].w);
            u.z = pack2(f1[j].x, f1[j].y);  u.w = pack2(f1[j].z, f1[j].w);
            *reinterpret_cast<uint4*>(smem + SX_B + r * LDA + c8 * 16) = u;
        }
        CP_WAIT0();
        __syncthreads();
    }

    const int n01 = wn * 48;

#pragma unroll 1
    for (int half = 0; half < 2; half++) {
        const size_t b = b0 + half;
        if ((int)b >= B) break;
        const float* xb = x + b * (size_t)(T_SEQ * E_DIM);

        // =============== Phase 1: QKV = x @ Wt (W resident, x single-buffered) ===============
        float acc1[2][6][4];
#pragma unroll
        for (int i = 0; i < 2; i++)
#pragma unroll
            for (int j = 0; j < 6; j++)
#pragma unroll
                for (int r = 0; r < 4; r++) acc1[i][j][r] = 0.f;

        const uint32_t arow = sbase + SX_B + (m0 + (lane & 15)) * LDA + (lane >> 4) * 16;
        const uint32_t brow0 = sbase + SW_B
                             + (n01 + ((lane >> 4) << 3) + (lane & 7)) * LDW
                             + ((lane >> 3) & 1) * 16;

#pragma unroll 1
        for (int ec = 0; ec < 4; ec++) {
            // prefetch next chunk into regs: (half, ec+1), or (half+1, chunk0) at ec==3
            const bool hasnext = !(half == 1 && ec == 3);
            float4 f0[2], f1[2];
            if (hasnext) {
                size_t bn = (ec == 3) ? (((int)(b + 1) < B) ? b + 1 : b) : b;
                int ecn = (ec + 1) & 3;
                const float* xn = x + bn * (size_t)(T_SEQ * E_DIM) + ecn * 64;
#pragma unroll
                for (int j = 0; j < 2; j++) {
                    int q = tid + j * 512, r = q >> 3, c8 = q & 7;
                    const float* p = xn + r * E_DIM + c8 * 8;
                    f0[j] = *reinterpret_cast<const float4*>(p);
                    f1[j] = *reinterpret_cast<const float4*>(p + 4);
                }
            }

            // MMA over current chunk (K=64 -> 4 k16 steps)
            const uint32_t brow = brow0 + (uint32_t)ec * W_EC;
#pragma unroll
            for (int kt = 0; kt < 4; kt++) {
                uint32_t a[2][4], bf[3][4];
#pragma unroll
                for (int mt = 0; mt < 2; mt++) LDSM_X4(a[mt], arow + mt * 16 * LDA + kt * 32);
#pragma unroll
                for (int bt = 0; bt < 3; bt++) LDSM_X4(bf[bt], brow + bt * 16 * LDW + kt * 32);
#pragma unroll
                for (int mt = 0; mt < 2; mt++)
#pragma unroll
                    for (int nt = 0; nt < 6; nt++)
                        MMA16816(acc1[mt][nt], a[mt], bf[nt >> 1][(nt & 1) * 2],
                                 bf[nt >> 1][(nt & 1) * 2 + 1]);
            }
            __syncthreads();              // all warps done reading SX
            if (hasnext) {
#pragma unroll
                for (int j = 0; j < 2; j++) {
                    int q = tid + j * 512, r = q >> 3, c8 = q & 7;
                    uint4 u;
                    u.x = pack2(f0[j].x, f0[j].y);  u.y = pack2(f0[j].z, f0[j].w);
                    u.z = pack2(f1[j].x, f1[j].y);  u.w = pack2(f1[j].z, f1[j].w);
                    *reinterpret_cast<uint4*>(smem + SX_B + r * LDA + c8 * 16) = u;
                }
                __syncthreads();          // publish next chunk
            }
        }

        // epilogue 1: acc -> fp16 Q/K/V tiles
#pragma unroll
        for (int mt = 0; mt < 2; mt++) {
            int rlo = m0 + mt * 16 + g, rhi = rlo + 8;
#pragma unroll
            for (int nt = 0; nt < 6; nt++) {
                int cg = n01 + nt * 8 + t * 2;
                int sel = cg >> 6, cl = cg & 63;
                uint32_t base = (sel == 0) ? SQ_B : (sel == 1) ? SK_B : SV_B;
                *reinterpret_cast<uint32_t*>(smem + base + rlo * LDA + cl * 2) =
                    pack2(acc1[mt][nt][0], acc1[mt][nt][1]);
                *reinterpret_cast<uint32_t*>(smem + base + rhi * LDA + cl * 2) =
                    pack2(acc1[mt][nt][2], acc1[mt][nt][3]);
            }
        }
        __syncthreads();

        // =============== Phase 2a: S = Q @ K^T, causal softmax -> P ===============
        const int n02 = wn * 32;
        const bool active = (n02 <= m0 + 31);     // wn <= wm
        float acc2[2][4][4];
        float fscale[2][2];

        if (active) {
#pragma unroll
            for (int i = 0; i < 2; i++)
#pragma unroll
                for (int j = 0; j < 4; j++)
#pragma unroll
                    for (int r = 0; r < 4; r++) acc2[i][j][r] = 0.f;

            const uint32_t aq = sbase + SQ_B + (m0 + (lane & 15)) * LDA + (lane >> 4) * 16;
            const uint32_t bk = sbase + SK_B + (n02 + ((lane >> 4) << 3) + (lane & 7)) * LDA
                                            + ((lane >> 3) & 1) * 16;
#pragma unroll
            for (int kt = 0; kt < 4; kt++) {
                uint32_t a[2][4], bf[2][4];
#pragma unroll
                for (int mt = 0; mt < 2; mt++) LDSM_X4(a[mt], aq + mt * 16 * LDA + kt * 32);
#pragma unroll
                for (int bt = 0; bt < 2; bt++) LDSM_X4(bf[bt], bk + bt * 16 * LDA + kt * 32);
#pragma unroll
                for (int mt = 0; mt < 2; mt++)
#pragma unroll
                    for (int nt = 0; nt < 4; nt++)
                        MMA16816(acc2[mt][nt], a[mt], bf[nt >> 1][(nt & 1) * 2],
                                 bf[nt >> 1][(nt & 1) * 2 + 1]);
            }

#pragma unroll
            for (int mt = 0; mt < 2; mt++) {
                int rlo = m0 + mt * 16 + g, rhi = rlo + 8;
                float mlo = -1e30f, mhi = -1e30f;
#pragma unroll
                for (int nt = 0; nt < 4; nt++)
#pragma unroll
                    for (int j = 0; j < 2; j++) {
                        int c = n02 + nt * 8 + t * 2 + j;
                        float v0 = acc2[mt][nt][j] * SCL;
                        v0 = (c <= rlo) ? v0 : -1e30f;
                        acc2[mt][nt][j] = v0; mlo = fmaxf(mlo, v0);
                        float v1 = acc2[mt][nt][2 + j] * SCL;
                        v1 = (c <= rhi) ? v1 : -1e30f;
                        acc2[mt][nt][2 + j] = v1; mhi = fmaxf(mhi, v1);
                    }
                mlo = fmaxf(mlo, __shfl_xor_sync(0xffffffffu, mlo, 1));
                mlo = fmaxf(mlo, __shfl_xor_sync(0xffffffffu, mlo, 2));
                mhi = fmaxf(mhi, __shfl_xor_sync(0xffffffffu, mhi, 1));
                mhi = fmaxf(mhi, __shfl_xor_sync(0xffffffffu, mhi, 2));
                float slo = 0.f, shi = 0.f;
#pragma unroll
                for (int nt = 0; nt < 4; nt++)
#pragma unroll
                    for (int j = 0; j < 2; j++) {
                        float e0 = fex2(acc2[mt][nt][j] - mlo);
                        float e1 = fex2(acc2[mt][nt][2 + j] - mhi);
                        acc2[mt][nt][j] = e0;  acc2[mt][nt][2 + j] = e1;
                        slo += e0; shi += e1;
                    }
                slo += __shfl_xor_sync(0xffffffffu, slo, 1);
                slo += __shfl_xor_sync(0xffffffffu, slo, 2);
                shi += __shfl_xor_sync(0xffffffffu, shi, 1);
                shi += __shfl_xor_sync(0xffffffffu, shi, 2);
                if (t == 0) {
                    pm[wn * 128 + rlo] = mlo;  pm[wn * 128 + rhi] = mhi;
                    ps[wn * 128 + rlo] = slo;  ps[wn * 128 + rhi] = shi;
                }
                fscale[mt][0] = mlo;  fscale[mt][1] = mhi;
            }
        } else {
            if (t == 0) {
#pragma unroll
                for (int mt = 0; mt < 2; mt++) {
                    int rlo = m0 + mt * 16 + g, rhi = rlo + 8;
                    pm[wn * 128 + rlo] = -1e30f;  pm[wn * 128 + rhi] = -1e30f;
                    ps[wn * 128 + rlo] = 0.f;     ps[wn * 128 + rhi] = 0.f;
                }
            }
        }
        __syncthreads();

        // combine partials, write P (fp16); inactive tiles never read by kt-skipped PV
        if (active) {
#pragma unroll
            for (int mt = 0; mt < 2; mt++) {
                int rlo = m0 + mt * 16 + g, rhi = rlo + 8;
                float M0 = pm[rlo], M1 = pm[128 + rlo], M2 = pm[256 + rlo], M3 = pm[384 + rlo];
                float Mlo = fmaxf(fmaxf(M0, M1), fmaxf(M2, M3));
                float Zlo = ps[rlo] * fex2(M0 - Mlo) + ps[128 + rlo] * fex2(M1 - Mlo)
                          + ps[256 + rlo] * fex2(M2 - Mlo) + ps[384 + rlo] * fex2(M3 - Mlo);
                float N0 = pm[rhi], N1 = pm[128 + rhi], N2 = pm[256 + rhi], N3 = pm[384 + rhi];
                float Mhi = fmaxf(fmaxf(N0, N1), fmaxf(N2, N3));
                float Zhi = ps[rhi] * fex2(N0 - Mhi) + ps[128 + rhi] * fex2(N1 - Mhi)
                          + ps[256 + rhi] * fex2(N2 - Mhi) + ps[384 + rhi] * fex2(N3 - Mhi);
                float flo = fex2(fscale[mt][0] - Mlo) / Zlo;
                float fhi = fex2(fscale[mt][1] - Mhi) / Zhi;
#pragma unroll
                for (int nt = 0; nt < 4; nt++) {
                    int c = n02 + nt * 8 + t * 2;
                    *reinterpret_cast<uint32_t*>(smem + SP_B + rlo * LDP + c * 2) =
                        pack2(acc2[mt][nt][0] * flo, acc2[mt][nt][1] * flo);
                    *reinterpret_cast<uint32_t*>(smem + SP_B + rhi * LDP + c * 2) =
                        pack2(acc2[mt][nt][2] * fhi, acc2[mt][nt][3] * fhi);
                }
            }
        }
        __syncthreads();

        // =============== Phase 2c: O = P @ V  (causal kt-skip) ===============
        const int n03 = wn * 16;
        float acc3[2][2][4];
#pragma unroll
        for (int i = 0; i < 2; i++)
#pragma unroll
            for (int j = 0; j < 2; j++)
#pragma unroll
                for (int r = 0; r < 4; r++) acc3[i][j][r] = 0.f;

        const uint32_t prow = sbase + SP_B + (m0 + (lane & 15)) * LDP + (lane >> 4) * 16;
        const uint32_t vbase = sbase + SV_B
                             + (((lane >> 3) & 1) * 8 + (lane & 7)) * LDA
                             + (lane >> 4) * 16 + n03 * 2;
        const int ktend = 2 * wm + 2;     // P cols beyond m0+31 are exactly zero
#pragma unroll 2
        for (int kt = 0; kt < ktend; kt++) {
            uint32_t a3[2][4], bv[4];
#pragma unroll
            for (int mt = 0; mt < 2; mt++) LDSM_X4(a3[mt], prow + mt * 16 * LDP + kt * 32);
            LDSM_X4T(bv, vbase + kt * 16 * LDA);
#pragma unroll
            for (int mt = 0; mt < 2; mt++) {
                MMA16816(acc3[mt][0], a3[mt], bv[0], bv[1]);
                MMA16816(acc3[mt][1], a3[mt], bv[2], bv[3]);
            }
        }

        // output: fp32 float2 stores
        float* ob = out + b * (size_t)(T_SEQ * H_DIM);
#pragma unroll
        for (int mt = 0; mt < 2; mt++) {
            int rlo = m0 + mt * 16 + g, rhi = rlo + 8;
#pragma unroll
            for (int nt = 0; nt < 2; nt++) {
                int c = n03 + nt * 8 + t * 2;
                *reinterpret_cast<float2*>(ob + rlo * H_DIM + c) =
                    make_float2(acc3[mt][nt][0], acc3[mt][nt][1]);
                *reinterpret_cast<float2*>(ob + rhi * H_DIM + c) =
                    make_float2(acc3[mt][nt][2], acc3[mt][nt][3]);
            }
        }
        __syncthreads();   // SQ/SK/SV free for next batch's epilogue; SX already staged
    }
}

extern "C" void kernel_launch(void* const* d_in, const int* in_sizes, int n_in,
                              void* d_out, int out_size) {
    const float* x  = (const float*)d_in[0];
    const float* Wq = (const float*)d_in[1];
    const float* Wk = (const float*)d_in[2];
    const float* Wv = (const float*)d_in[3];
    float* out = (float*)d_out;

    int B = in_sizes[0] / (T_SEQ * E_DIM);   // 4096

    cudaFuncSetAttribute(attn_fp16_kernel,
                         cudaFuncAttributeMaxDynamicSharedMemorySize,
                         (int)SMEM_BYTES);

    prep_w_kernel<<<12, 256>>>(Wq, Wk, Wv);
    attn_fp16_kernel<<<(B + 1) / 2, 512, SMEM_BYTES>>>(x, out, B);
}